// round 8
// baseline (speedup 1.0000x reference)
#include <cuda_runtime.h>
#include <cstddef>

#define NATOMS 512
#define DDIM   128
#define KDIM   1536   // 3*N
#define NSTR   6
#define KTOT   (KDIM + NSTR + 1)
#define NSPEC  4
#define TILE   4      // atoms per MLP block
#define XS     132    // activation smem row stride (floats)
#define WS     130    // weight smem row stride (floats)
#define WS64   65     // same, in u64 units
#define NTILES_MAX (NATOMS / TILE + NSPEC - 1)   // 131

typedef unsigned long long u64;

#define FMA_F32X2(d, a, b, c) \
    asm("fma.rn.f32x2 %0, %1, %2, %3;" : "=l"(d) : "l"(a), "l"(b), "l"(c))
#define PACK_F32X2(out, lo, hi) \
    asm("mov.b64 %0, {%1, %2};" : "=l"(out) : "r"(__float_as_uint(lo)), "r"(__float_as_uint(hi)))

__device__ __forceinline__ float f32x2_lo(u64 v) { return __uint_as_float((unsigned)(v & 0xFFFFFFFFu)); }
__device__ __forceinline__ float f32x2_hi(u64 v) { return __uint_as_float((unsigned)(v >> 32)); }
__device__ __forceinline__ float f32x2_sum(u64 v) { return f32x2_lo(v) + f32x2_hi(v); }

// Scratch
__device__ __align__(16) float g_partial[KDIM * NATOMS];        // force partials (3 MB)
__device__ __align__(16) float g_separt[(NSTR + 1) * NATOMS];   // stress + energy partials
__device__ __align__(16) float g_G[NATOMS * DDIM];              // per-atom dE/ddesc
__device__ int g_flag[NATOMS];                                  // per-atom G-ready flags (0-init)

// ---------------------------------------------------------------------------
// Kernel 1: species-batched MLP fwd+bwd (latency-trimmed) + PDL trigger.
// ---------------------------------------------------------------------------
__global__ __launch_bounds__(256) void nnp_mlp_kernel(
    const float* __restrict__ desc,   // [N, D]
    const float* __restrict__ SG,     // [N, 6, D]
    const float* __restrict__ W0,     // [S, H, D]
    const float* __restrict__ b0,     // [S, H]
    const float* __restrict__ W1,     // [S, H, H]
    const float* __restrict__ b1,     // [S, H]
    const float* __restrict__ W2,     // [S, 1, H]
    const float* __restrict__ b2,     // [S, 1]
    const int*   __restrict__ species)
{
    // Let the dependent (stream) kernel launch immediately — all 131 blocks
    // fit in wave 1, so this fires at grid start.
    asm volatile("griddepcontrol.launch_dependents;");

    const int tid  = threadIdx.x;
    const int ty   = tid >> 2;     // 0..63 -> rows ty*2, ty*2+1
    const int tx   = tid & 3;      // atom within tile
    const int wid  = tid >> 5;
    const int lane = tid & 31;
    const int rbase = ty * 2;

    extern __shared__ float sm[];
    float* W0s = sm;                      // 128*130 floats
    float* W1s = sm + DDIM * WS;          // 128*130 floats
    float* X   = sm + 2 * DDIM * WS;      // TILE*XS
    float* H0  = X  + TILE * XS;          // h0, later G
    float* A0  = H0 + TILE * XS;          // 1-h0^2, later d0
    float* D1  = A0 + TILE * XS;
    float* Ep  = D1 + TILE * XS;          // 256
    __shared__ int sSpec[NATOMS];
    __shared__ int idx[TILE];
    __shared__ int sh_cnt[NSPEC];
    __shared__ int sh_s, sh_j, sh_m;

    // ---- coalesced species preload (all warps) ----
    sSpec[tid]       = species[tid];
    sSpec[tid + 256] = species[tid + 256];
    __syncthreads();

    // ---- pass 1: counts from smem (warp 0) ----
    if (wid == 0) {
        int c0 = 0, c1 = 0, c2 = 0, c3 = 0;
        #pragma unroll
        for (int c = 0; c < NATOMS; c += 32) {
            const int spv = sSpec[c + lane];
            c0 += __popc(__ballot_sync(0xFFFFFFFFu, spv == 0));
            c1 += __popc(__ballot_sync(0xFFFFFFFFu, spv == 1));
            c2 += __popc(__ballot_sync(0xFFFFFFFFu, spv == 2));
            c3 += __popc(__ballot_sync(0xFFFFFFFFu, spv == 3));
        }
        if (lane == 0) { sh_cnt[0] = c0; sh_cnt[1] = c1; sh_cnt[2] = c2; sh_cnt[3] = c3; }
    }
    __syncthreads();

    if (tid == 0) {
        int b = blockIdx.x, sp = 0, acc = 0;
        for (; sp < NSPEC; sp++) {
            const int t = (sh_cnt[sp] + TILE - 1) / TILE;
            if (b < acc + t) break;
            acc += t;
        }
        sh_s = sp;
        if (sp < NSPEC) {
            const int jj = b - acc;
            sh_j = jj;
            const int mm = sh_cnt[sp] - jj * TILE;
            sh_m = mm > TILE ? TILE : mm;
        }
    }
    __syncthreads();
    const int s = sh_s;
    if (s >= NSPEC) return;       // slack block
    const int j = sh_j;
    const int m = sh_m;

    // ---- prefetch biases for my rows (overlaps with everything below) ----
    const float pb0a = b0[s * DDIM + rbase + 0], pb0b = b0[s * DDIM + rbase + 1];
    const float pb1a = b1[s * DDIM + rbase + 0], pb1b = b1[s * DDIM + rbase + 1];
    const float pw2a = W2[s * DDIM + rbase + 0], pw2b = W2[s * DDIM + rbase + 1];
    const float pb2  = b2[s];

    // ---- pass 2: atom indices from smem (warp 0) ----
    if (wid == 0) {
        int base = 0;
        #pragma unroll
        for (int c = 0; c < NATOMS; c += 32) {
            const int spv = sSpec[c + lane];
            const unsigned mask = __ballot_sync(0xFFFFFFFFu, spv == s);
            if (spv == s) {
                const int rank = base + __popc(mask & ((1u << lane) - 1u));
                const int rel = rank - j * TILE;
                if (rel >= 0 && rel < TILE) idx[rel] = c + lane;
            }
            base += __popc(mask);
        }
    }
    __syncthreads();

    // ---- prefetch SG stress rows into registers (latency hidden by staging) ----
    float4 sv[3]; int srs[3], sn[3], sa[3]; bool svd[3];
    #pragma unroll
    for (int q = 0; q < 3; q++) {
        const int t = wid + q * 8;
        svd[q] = t < NSTR * m;
        srs[q] = 0; sn[q] = 0; sa[q] = 0;
        if (svd[q]) {
            sa[q] = t / NSTR; srs[q] = t % NSTR; sn[q] = idx[sa[q]];
            sv[q] = ((const float4*)(SG + ((size_t)sn[q] * NSTR + srs[q]) * DDIM))[lane];
        }
    }

    // ---- stage descriptors + W0/W1 ----
    for (int e = tid; e < TILE * DDIM; e += 256) {
        const int a = e >> 7, d = e & 127;
        X[a * XS + d] = (a < m) ? desc[(size_t)idx[a] * DDIM + d] : 0.f;
    }
    {
        const float2* w0g = (const float2*)(W0 + (size_t)s * DDIM * DDIM);
        const float2* w1g = (const float2*)(W1 + (size_t)s * DDIM * DDIM);
        #pragma unroll 8
        for (int f = tid; f < DDIM * 64; f += 256) {
            const int r = f >> 6, d2 = f & 63;
            *(float2*)(W0s + r * WS + d2 * 2) = w0g[f];
            *(float2*)(W1s + r * WS + d2 * 2) = w1g[f];
        }
    }
    __syncthreads();

    // ---- forward layer 0 ----
    {
        u64 acc0 = 0ull, acc1 = 0ull;
        const u64* Xd = (const u64*)(X + tx * XS);
        const u64* Wd = (const u64*)W0s;
        #pragma unroll 8
        for (int dq = 0; dq < 64; dq++) {
            const u64 xv = Xd[dq];
            FMA_F32X2(acc0, Wd[(size_t)(rbase + 0) * WS64 + dq], xv, acc0);
            FMA_F32X2(acc1, Wd[(size_t)(rbase + 1) * WS64 + dq], xv, acc1);
        }
        const float h0v = tanhf(f32x2_sum(acc0) + pb0a);
        const float h1v = tanhf(f32x2_sum(acc1) + pb0b);
        H0[tx * XS + rbase + 0] = h0v;  A0[tx * XS + rbase + 0] = 1.f - h0v * h0v;
        H0[tx * XS + rbase + 1] = h1v;  A0[tx * XS + rbase + 1] = 1.f - h1v * h1v;
    }
    __syncthreads();

    // ---- forward layer 1 + output partials ----
    {
        u64 acc0 = 0ull, acc1 = 0ull;
        const u64* Xd = (const u64*)(H0 + tx * XS);
        const u64* Wd = (const u64*)W1s;
        #pragma unroll 8
        for (int dq = 0; dq < 64; dq++) {
            const u64 xv = Xd[dq];
            FMA_F32X2(acc0, Wd[(size_t)(rbase + 0) * WS64 + dq], xv, acc0);
            FMA_F32X2(acc1, Wd[(size_t)(rbase + 1) * WS64 + dq], xv, acc1);
        }
        const float h0v = tanhf(f32x2_sum(acc0) + pb1a);
        const float h1v = tanhf(f32x2_sum(acc1) + pb1b);
        Ep[tid] = pw2a * h0v + pw2b * h1v;
        D1[tx * XS + rbase + 0] = pw2a * (1.f - h0v * h0v);
        D1[tx * XS + rbase + 1] = pw2b * (1.f - h1v * h1v);
    }
    __syncthreads();

    // ---- energy per atom ----
    if (tid < m) {
        float e = pb2;
        #pragma unroll
        for (int t2 = 0; t2 < 64; t2++) e += Ep[t2 * 4 + tid];
        g_separt[NSTR * NATOMS + idx[tid]] = e;
    }

    // ---- backward: D0 = (W1^T @ D1) * A0 ----
    {
        u64 acca = 0ull, accb = 0ull;
        const float* d1p = D1 + tx * XS;
        #pragma unroll 4
        for (int jj = 0; jj < DDIM; jj += 2) {
            const float dva = d1p[jj], dvb = d1p[jj + 1];
            u64 da, db; PACK_F32X2(da, dva, dva); PACK_F32X2(db, dvb, dvb);
            FMA_F32X2(acca, *(const u64*)(W1s + (size_t)jj * WS + rbase), da, acca);
            FMA_F32X2(accb, *(const u64*)(W1s + (size_t)(jj + 1) * WS + rbase), db, accb);
        }
        A0[tx * XS + rbase + 0] *= f32x2_lo(acca) + f32x2_lo(accb);
        A0[tx * XS + rbase + 1] *= f32x2_hi(acca) + f32x2_hi(accb);
    }
    __syncthreads();

    // ---- backward: G = W0^T @ D0 -> H0 (reused) + g_G ----
    {
        u64 acca = 0ull, accb = 0ull;
        const float* d0p = A0 + tx * XS;
        #pragma unroll 4
        for (int jj = 0; jj < DDIM; jj += 2) {
            const float dva = d0p[jj], dvb = d0p[jj + 1];
            u64 da, db; PACK_F32X2(da, dva, dva); PACK_F32X2(db, dvb, dvb);
            FMA_F32X2(acca, *(const u64*)(W0s + (size_t)jj * WS + rbase), da, acca);
            FMA_F32X2(accb, *(const u64*)(W0s + (size_t)(jj + 1) * WS + rbase), db, accb);
        }
        const float g0 = f32x2_lo(acca) + f32x2_lo(accb);
        const float g1 = f32x2_hi(acca) + f32x2_hi(accb);
        H0[tx * XS + rbase + 0] = g0;
        H0[tx * XS + rbase + 1] = g1;
        if (tx < m)
            *(float2*)(g_G + (size_t)idx[tx] * DDIM + rbase) = make_float2(g0, g1);
    }
    __syncthreads();

    // ---- release per-atom flags (G fully written + visible) ----
    if (tid < m) {
        __threadfence();
        ((volatile int*)g_flag)[idx[tid]] = 1;
    }

    // ---- stress partials (SG already in registers) ----
    #pragma unroll
    for (int q = 0; q < 3; q++) {
        if (svd[q]) {
            const float4 g = ((const float4*)(H0 + sa[q] * XS))[lane];
            float svv = sv[q].x * g.x + sv[q].y * g.y + sv[q].z * g.z + sv[q].w * g.w;
            #pragma unroll
            for (int off = 16; off > 0; off >>= 1)
                svv += __shfl_xor_sync(0xFFFFFFFFu, svv, off);
            if (lane == 0) g_separt[(size_t)srs[q] * NATOMS + sn[q]] = svv;
        }
    }
}

// ---------------------------------------------------------------------------
// Kernel 2: stream coord_grads (403 MB). Launched with PDL — co-resides with
// the MLP, prefetches its first CG batch, then waits on the atom's flag.
// ---------------------------------------------------------------------------
__global__ __launch_bounds__(256) void nnp_stream_kernel(
    const float* __restrict__ CG)     // [N, KDIM, D]
{
    const int b    = blockIdx.x;
    const int n    = b / 6;
    const int chnk = b % 6;
    const int wid  = threadIdx.x >> 5;
    const int lane = threadIdx.x & 31;

    const int k0 = chnk * 256 + wid * 32;
    const float4* base = reinterpret_cast<const float4*>(
        CG + ((size_t)n * KDIM + k0) * DDIM);

    // prefetch iteration 0 (independent of G)
    const float4* p0 = base + lane;
    float4 u0 = __ldcs(p0 + 0 * 32);
    float4 u1 = __ldcs(p0 + 1 * 32);
    float4 u2 = __ldcs(p0 + 2 * 32);
    float4 u3 = __ldcs(p0 + 3 * 32);

    // wait for this atom's G
    if (((volatile int*)g_flag)[n] == 0) {
        while (((volatile int*)g_flag)[n] == 0) __nanosleep(64);
    }
    __threadfence();

    const float4 gv = reinterpret_cast<const float4*>(g_G + (size_t)n * DDIM)[lane];
    float* outp = g_partial + (size_t)k0 * NATOMS + n;

    // iteration 0 (prefetched)
    {
        float s0 = u0.x * gv.x + u0.y * gv.y + u0.z * gv.z + u0.w * gv.w;
        float s1 = u1.x * gv.x + u1.y * gv.y + u1.z * gv.z + u1.w * gv.w;
        float s2 = u2.x * gv.x + u2.y * gv.y + u2.z * gv.z + u2.w * gv.w;
        float s3 = u3.x * gv.x + u3.y * gv.y + u3.z * gv.z + u3.w * gv.w;
        #pragma unroll
        for (int off = 16; off > 0; off >>= 1) {
            s0 += __shfl_xor_sync(0xFFFFFFFFu, s0, off);
            s1 += __shfl_xor_sync(0xFFFFFFFFu, s1, off);
            s2 += __shfl_xor_sync(0xFFFFFFFFu, s2, off);
            s3 += __shfl_xor_sync(0xFFFFFFFFu, s3, off);
        }
        if (lane == 0) {
            outp[0 * NATOMS] = s0;
            outp[1 * NATOMS] = s1;
            outp[2 * NATOMS] = s2;
            outp[3 * NATOMS] = s3;
        }
    }

    #pragma unroll
    for (int it = 1; it < 8; it++) {
        const float4* p = base + (size_t)(it * 4) * 32 + lane;
        float4 v0 = __ldcs(p + 0 * 32);
        float4 v1 = __ldcs(p + 1 * 32);
        float4 v2 = __ldcs(p + 2 * 32);
        float4 v3 = __ldcs(p + 3 * 32);
        float s0 = v0.x * gv.x + v0.y * gv.y + v0.z * gv.z + v0.w * gv.w;
        float s1 = v1.x * gv.x + v1.y * gv.y + v1.z * gv.z + v1.w * gv.w;
        float s2 = v2.x * gv.x + v2.y * gv.y + v2.z * gv.z + v2.w * gv.w;
        float s3 = v3.x * gv.x + v3.y * gv.y + v3.z * gv.z + v3.w * gv.w;
        #pragma unroll
        for (int off = 16; off > 0; off >>= 1) {
            s0 += __shfl_xor_sync(0xFFFFFFFFu, s0, off);
            s1 += __shfl_xor_sync(0xFFFFFFFFu, s1, off);
            s2 += __shfl_xor_sync(0xFFFFFFFFu, s2, off);
            s3 += __shfl_xor_sync(0xFFFFFFFFu, s3, off);
        }
        if (lane == 0) {
            outp[(size_t)(it * 4 + 0) * NATOMS] = s0;
            outp[(size_t)(it * 4 + 1) * NATOMS] = s1;
            outp[(size_t)(it * 4 + 2) * NATOMS] = s2;
            outp[(size_t)(it * 4 + 3) * NATOMS] = s3;
        }
    }
}

// ---------------------------------------------------------------------------
// Kernel 3: deterministic reduce + flag reset (for next graph replay).
// ---------------------------------------------------------------------------
__global__ void nnp_reduce_kernel(float* __restrict__ out,
                                  const float* __restrict__ volume)
{
    if (blockIdx.x == 0) {
        g_flag[threadIdx.x]       = 0;
        g_flag[threadIdx.x + 256] = 0;
    }

    const int k    = blockIdx.x * 8 + (threadIdx.x >> 5);
    const int lane = threadIdx.x & 31;
    if (k >= KTOT) return;

    const float* src = (k < KDIM) ? (g_partial + (size_t)k * NATOMS)
                                  : (g_separt + (size_t)(k - KDIM) * NATOMS);
    const float4* base = reinterpret_cast<const float4*>(src);
    float4 v0 = base[lane + 0 * 32];
    float4 v1 = base[lane + 1 * 32];
    float4 v2 = base[lane + 2 * 32];
    float4 v3 = base[lane + 3 * 32];
    float s = (v0.x + v0.y + v0.z + v0.w) + (v1.x + v1.y + v1.z + v1.w)
            + (v2.x + v2.y + v2.z + v2.w) + (v3.x + v3.y + v3.z + v3.w);
    #pragma unroll
    for (int off = 16; off > 0; off >>= 1)
        s += __shfl_xor_sync(0xFFFFFFFFu, s, off);

    if (lane == 0) {
        if (k < KDIM)             out[1 + k] = s;
        else if (k < KDIM + NSTR) out[1 + KDIM + (k - KDIM)] = -s / volume[0];
        else                      out[0] = s;
    }
}

extern "C" void kernel_launch(void* const* d_in, const int* in_sizes, int n_in,
                              void* d_out, int out_size)
{
    const float* desc    = (const float*)d_in[0];
    const float* CG      = (const float*)d_in[1];
    const float* SG      = (const float*)d_in[2];
    const float* W0      = (const float*)d_in[3];
    const float* b0      = (const float*)d_in[4];
    const float* W1      = (const float*)d_in[5];
    const float* b1      = (const float*)d_in[6];
    const float* W2      = (const float*)d_in[7];
    const float* b2      = (const float*)d_in[8];
    const float* volume  = (const float*)d_in[9];
    const int*   species = (const int*)  d_in[10];
    float* out = (float*)d_out;

    const int mlp_smem = (2 * DDIM * WS + 4 * TILE * XS + 256) * sizeof(float); // ~142 KB
    cudaFuncSetAttribute(nnp_mlp_kernel,
                         cudaFuncAttributeMaxDynamicSharedMemorySize, mlp_smem);

    nnp_mlp_kernel<<<NTILES_MAX, 256, mlp_smem>>>(desc, SG, W0, b0, W1, b1, W2, b2, species);

    // Stream kernel with programmatic dependent launch (overlaps with MLP).
    cudaLaunchConfig_t cfg = {};
    cfg.gridDim  = dim3(NATOMS * 6);
    cfg.blockDim = dim3(256);
    cfg.dynamicSmemBytes = 0;
    cfg.stream = 0;
    cudaLaunchAttribute attrs[1];
    attrs[0].id = cudaLaunchAttributeProgrammaticStreamSerialization;
    attrs[0].val.programmaticStreamSerializationAllowed = 1;
    cfg.attrs = attrs;
    cfg.numAttrs = 1;
    cudaLaunchKernelEx(&cfg, nnp_stream_kernel, CG);

    nnp_reduce_kernel<<<(KTOT + 7) / 8, 256>>>(out, volume);
}

// round 9
// speedup vs baseline: 1.0556x; 1.0556x over previous
#include <cuda_runtime.h>
#include <cstddef>

#define NATOMS 512
#define DDIM   128
#define KDIM   1536   // 3*N
#define NSTR   6
#define KTOT   (KDIM + NSTR + 1)
#define NSPEC  4
#define TILE   4      // atoms per MLP block
#define XS     132    // activation smem row stride (floats)
#define WS     130    // weight smem row stride (floats)
#define WS64   65     // same, in u64 units
#define NTILES_MAX (NATOMS / TILE + NSPEC - 1)   // 131
#define MLP_THREADS 512

typedef unsigned long long u64;

#define FMA_F32X2(d, a, b, c) \
    asm("fma.rn.f32x2 %0, %1, %2, %3;" : "=l"(d) : "l"(a), "l"(b), "l"(c))

__device__ __forceinline__ float f32x2_lo(u64 v) { return __uint_as_float((unsigned)(v & 0xFFFFFFFFu)); }
__device__ __forceinline__ float f32x2_hi(u64 v) { return __uint_as_float((unsigned)(v >> 32)); }
__device__ __forceinline__ float f32x2_sum(u64 v) { return f32x2_lo(v) + f32x2_hi(v); }

// Scratch
__device__ __align__(16) float g_partial[KDIM * NATOMS];        // force partials (3 MB)
__device__ __align__(16) float g_separt[(NSTR + 1) * NATOMS];   // stress + energy partials
__device__ __align__(16) float g_G[NATOMS * DDIM];              // per-atom dE/ddesc

// ---------------------------------------------------------------------------
// Kernel 1: species-batched MLP fwd+bwd. 131 blocks x 512 threads.
// Thread (ty,tx): ty=tid>>2 -> one row (0..127); tx=tid&3 -> atom in tile.
// W0[s], W1[s] staged in smem with 130-float pitch.
// ---------------------------------------------------------------------------
__global__ __launch_bounds__(MLP_THREADS) void nnp_mlp_kernel(
    const float* __restrict__ desc,   // [N, D]
    const float* __restrict__ SG,     // [N, 6, D]
    const float* __restrict__ W0,     // [S, H, D]
    const float* __restrict__ b0,     // [S, H]
    const float* __restrict__ W1,     // [S, H, H]
    const float* __restrict__ b1,     // [S, H]
    const float* __restrict__ W2,     // [S, 1, H]
    const float* __restrict__ b2,     // [S, 1]
    const int*   __restrict__ species)
{
    const int tid  = threadIdx.x;
    const int ty   = tid >> 2;     // row 0..127
    const int tx   = tid & 3;      // atom within tile
    const int wid  = tid >> 5;     // 0..15
    const int lane = tid & 31;

    extern __shared__ float sm[];
    float* W0s = sm;                      // 128*130 floats
    float* W1s = sm + DDIM * WS;          // 128*130 floats
    float* X   = sm + 2 * DDIM * WS;      // TILE*XS
    float* H0  = X  + TILE * XS;          // h0, later G
    float* A0  = H0 + TILE * XS;          // 1-h0^2, later d0
    float* D1  = A0 + TILE * XS;
    float* Ep  = D1 + TILE * XS;          // 512 energy partials
    __shared__ int sSpec[NATOMS];
    __shared__ int idx[TILE];
    __shared__ int sh_cnt[NSPEC];
    __shared__ int sh_s, sh_j, sh_m;

    // ---- coalesced species preload (one shot, all threads) ----
    sSpec[tid] = species[tid];
    __syncthreads();

    // ---- pass 1: species counts from smem (warp 0) ----
    if (wid == 0) {
        int c0 = 0, c1 = 0, c2 = 0, c3 = 0;
        #pragma unroll
        for (int c = 0; c < NATOMS; c += 32) {
            const int spv = sSpec[c + lane];
            c0 += __popc(__ballot_sync(0xFFFFFFFFu, spv == 0));
            c1 += __popc(__ballot_sync(0xFFFFFFFFu, spv == 1));
            c2 += __popc(__ballot_sync(0xFFFFFFFFu, spv == 2));
            c3 += __popc(__ballot_sync(0xFFFFFFFFu, spv == 3));
        }
        if (lane == 0) { sh_cnt[0] = c0; sh_cnt[1] = c1; sh_cnt[2] = c2; sh_cnt[3] = c3; }
    }
    __syncthreads();

    if (tid == 0) {
        int b = blockIdx.x, sp = 0, acc = 0;
        for (; sp < NSPEC; sp++) {
            const int t = (sh_cnt[sp] + TILE - 1) / TILE;
            if (b < acc + t) break;
            acc += t;
        }
        sh_s = sp;
        if (sp < NSPEC) {
            const int jj = b - acc;
            sh_j = jj;
            const int mm = sh_cnt[sp] - jj * TILE;
            sh_m = mm > TILE ? TILE : mm;
        }
    }
    __syncthreads();
    const int s = sh_s;
    if (s >= NSPEC) return;       // slack block
    const int j = sh_j;
    const int m = sh_m;

    // ---- prefetch per-row biases (latency hidden by staging) ----
    const float pb0 = b0[s * DDIM + ty];
    const float pb1 = b1[s * DDIM + ty];
    const float pw2 = W2[s * DDIM + ty];
    const float pb2 = b2[s];

    // ---- pass 2: atom indices from smem (warp 0) ----
    if (wid == 0) {
        int base = 0;
        #pragma unroll
        for (int c = 0; c < NATOMS; c += 32) {
            const int spv = sSpec[c + lane];
            const unsigned mask = __ballot_sync(0xFFFFFFFFu, spv == s);
            if (spv == s) {
                const int rank = base + __popc(mask & ((1u << lane) - 1u));
                const int rel = rank - j * TILE;
                if (rel >= 0 && rel < TILE) idx[rel] = c + lane;
            }
            base += __popc(mask);
        }
    }
    __syncthreads();

    // ---- prefetch SG stress rows into registers ----
    float4 sv[2]; int srs[2], sn[2], sa[2]; bool svd[2];
    #pragma unroll
    for (int q = 0; q < 2; q++) {
        const int t = wid + q * 16;
        svd[q] = t < NSTR * m;
        srs[q] = 0; sn[q] = 0; sa[q] = 0;
        if (svd[q]) {
            sa[q] = t / NSTR; srs[q] = t % NSTR; sn[q] = idx[sa[q]];
            sv[q] = ((const float4*)(SG + ((size_t)sn[q] * NSTR + srs[q]) * DDIM))[lane];
        }
    }

    // ---- stage descriptors (1 elem/thread) + W0/W1 ----
    {
        const int a = tid >> 7, d = tid & 127;
        X[a * XS + d] = (a < m) ? desc[(size_t)idx[a] * DDIM + d] : 0.f;
    }
    {
        const float2* w0g = (const float2*)(W0 + (size_t)s * DDIM * DDIM);
        const float2* w1g = (const float2*)(W1 + (size_t)s * DDIM * DDIM);
        #pragma unroll 16
        for (int f = tid; f < DDIM * 64; f += MLP_THREADS) {
            const int r = f >> 6, d2 = f & 63;
            *(float2*)(W0s + r * WS + d2 * 2) = w0g[f];
            *(float2*)(W1s + r * WS + d2 * 2) = w1g[f];
        }
    }
    __syncthreads();

    // ---- forward layer 0: one row per thread, 2 indep chains ----
    {
        u64 acc0 = 0ull, acc1 = 0ull;
        const u64* Xd = (const u64*)(X + tx * XS);
        const u64* Wd = (const u64*)(W0s + (size_t)ty * WS);
        #pragma unroll 8
        for (int dq = 0; dq < 64; dq += 2) {
            FMA_F32X2(acc0, Wd[dq + 0], Xd[dq + 0], acc0);
            FMA_F32X2(acc1, Wd[dq + 1], Xd[dq + 1], acc1);
        }
        const float h = tanhf(f32x2_sum(acc0) + f32x2_sum(acc1) + pb0);
        H0[tx * XS + ty] = h;
        A0[tx * XS + ty] = 1.f - h * h;
    }
    __syncthreads();

    // ---- forward layer 1 + output partials ----
    {
        u64 acc0 = 0ull, acc1 = 0ull;
        const u64* Xd = (const u64*)(H0 + tx * XS);
        const u64* Wd = (const u64*)(W1s + (size_t)ty * WS);
        #pragma unroll 8
        for (int dq = 0; dq < 64; dq += 2) {
            FMA_F32X2(acc0, Wd[dq + 0], Xd[dq + 0], acc0);
            FMA_F32X2(acc1, Wd[dq + 1], Xd[dq + 1], acc1);
        }
        const float h = tanhf(f32x2_sum(acc0) + f32x2_sum(acc1) + pb1);
        Ep[tid] = pw2 * h;
        D1[tx * XS + ty] = pw2 * (1.f - h * h);
    }
    __syncthreads();

    // ---- energy per atom ----
    if (tid < m) {
        float e0 = pb2, e1 = 0.f, e2 = 0.f, e3 = 0.f;
        #pragma unroll 8
        for (int t2 = 0; t2 < 128; t2 += 4) {
            e0 += Ep[(t2 + 0) * 4 + tid];
            e1 += Ep[(t2 + 1) * 4 + tid];
            e2 += Ep[(t2 + 2) * 4 + tid];
            e3 += Ep[(t2 + 3) * 4 + tid];
        }
        g_separt[NSTR * NATOMS + idx[tid]] = (e0 + e1) + (e2 + e3);
    }

    // ---- backward: D0 = (W1^T @ D1) * A0 ----
    {
        float a0 = 0.f, a1 = 0.f, a2 = 0.f, a3 = 0.f;
        const float* d1p = D1 + tx * XS;
        const float* Wc  = W1s + ty;
        #pragma unroll 8
        for (int jj = 0; jj < DDIM; jj += 4) {
            a0 += Wc[(size_t)(jj + 0) * WS] * d1p[jj + 0];
            a1 += Wc[(size_t)(jj + 1) * WS] * d1p[jj + 1];
            a2 += Wc[(size_t)(jj + 2) * WS] * d1p[jj + 2];
            a3 += Wc[(size_t)(jj + 3) * WS] * d1p[jj + 3];
        }
        A0[tx * XS + ty] *= (a0 + a1) + (a2 + a3);
    }
    __syncthreads();

    // ---- backward: G = W0^T @ D0 -> H0 (reused) + g_G ----
    {
        float a0 = 0.f, a1 = 0.f, a2 = 0.f, a3 = 0.f;
        const float* d0p = A0 + tx * XS;
        const float* Wc  = W0s + ty;
        #pragma unroll 8
        for (int jj = 0; jj < DDIM; jj += 4) {
            a0 += Wc[(size_t)(jj + 0) * WS] * d0p[jj + 0];
            a1 += Wc[(size_t)(jj + 1) * WS] * d0p[jj + 1];
            a2 += Wc[(size_t)(jj + 2) * WS] * d0p[jj + 2];
            a3 += Wc[(size_t)(jj + 3) * WS] * d0p[jj + 3];
        }
        const float g = (a0 + a1) + (a2 + a3);
        H0[tx * XS + ty] = g;
        if (tx < m) g_G[(size_t)idx[tx] * DDIM + ty] = g;
    }
    __syncthreads();

    // ---- stress partials (SG in registers, 16 warps) ----
    #pragma unroll
    for (int q = 0; q < 2; q++) {
        if (svd[q]) {
            const float4 g = ((const float4*)(H0 + sa[q] * XS))[lane];
            float svv = sv[q].x * g.x + sv[q].y * g.y + sv[q].z * g.z + sv[q].w * g.w;
            #pragma unroll
            for (int off = 16; off > 0; off >>= 1)
                svv += __shfl_xor_sync(0xFFFFFFFFu, svv, off);
            if (lane == 0) g_separt[(size_t)srs[q] * NATOMS + sn[q]] = svv;
        }
    }
}

// ---------------------------------------------------------------------------
// Kernel 2: stream coord_grads (403 MB), atom-major — measured ~roofline.
// ---------------------------------------------------------------------------
__global__ __launch_bounds__(256) void nnp_stream_kernel(
    const float* __restrict__ CG)     // [N, KDIM, D]
{
    const int b    = blockIdx.x;
    const int n    = b / 6;
    const int chnk = b % 6;
    const int wid  = threadIdx.x >> 5;
    const int lane = threadIdx.x & 31;

    const float4 gv = reinterpret_cast<const float4*>(g_G + (size_t)n * DDIM)[lane];

    const int k0 = chnk * 256 + wid * 32;
    const float4* base = reinterpret_cast<const float4*>(
        CG + ((size_t)n * KDIM + k0) * DDIM);
    float* outp = g_partial + (size_t)k0 * NATOMS + n;

    #pragma unroll
    for (int it = 0; it < 8; it++) {
        const float4* p = base + (size_t)(it * 4) * 32 + lane;
        float4 v0 = __ldcs(p + 0 * 32);
        float4 v1 = __ldcs(p + 1 * 32);
        float4 v2 = __ldcs(p + 2 * 32);
        float4 v3 = __ldcs(p + 3 * 32);
        float s0 = v0.x * gv.x + v0.y * gv.y + v0.z * gv.z + v0.w * gv.w;
        float s1 = v1.x * gv.x + v1.y * gv.y + v1.z * gv.z + v1.w * gv.w;
        float s2 = v2.x * gv.x + v2.y * gv.y + v2.z * gv.z + v2.w * gv.w;
        float s3 = v3.x * gv.x + v3.y * gv.y + v3.z * gv.z + v3.w * gv.w;
        #pragma unroll
        for (int off = 16; off > 0; off >>= 1) {
            s0 += __shfl_xor_sync(0xFFFFFFFFu, s0, off);
            s1 += __shfl_xor_sync(0xFFFFFFFFu, s1, off);
            s2 += __shfl_xor_sync(0xFFFFFFFFu, s2, off);
            s3 += __shfl_xor_sync(0xFFFFFFFFu, s3, off);
        }
        if (lane == 0) {
            outp[(size_t)(it * 4 + 0) * NATOMS] = s0;
            outp[(size_t)(it * 4 + 1) * NATOMS] = s1;
            outp[(size_t)(it * 4 + 2) * NATOMS] = s2;
            outp[(size_t)(it * 4 + 3) * NATOMS] = s3;
        }
    }
}

// ---------------------------------------------------------------------------
// Kernel 3: deterministic reduce. Warp per output slot over 512 atoms.
// ---------------------------------------------------------------------------
__global__ void nnp_reduce_kernel(float* __restrict__ out,
                                  const float* __restrict__ volume)
{
    const int k    = blockIdx.x * 8 + (threadIdx.x >> 5);
    const int lane = threadIdx.x & 31;
    if (k >= KTOT) return;

    const float* src = (k < KDIM) ? (g_partial + (size_t)k * NATOMS)
                                  : (g_separt + (size_t)(k - KDIM) * NATOMS);
    const float4* base = reinterpret_cast<const float4*>(src);
    float4 v0 = base[lane + 0 * 32];
    float4 v1 = base[lane + 1 * 32];
    float4 v2 = base[lane + 2 * 32];
    float4 v3 = base[lane + 3 * 32];
    float s = (v0.x + v0.y + v0.z + v0.w) + (v1.x + v1.y + v1.z + v1.w)
            + (v2.x + v2.y + v2.z + v2.w) + (v3.x + v3.y + v3.z + v3.w);
    #pragma unroll
    for (int off = 16; off > 0; off >>= 1)
        s += __shfl_xor_sync(0xFFFFFFFFu, s, off);

    if (lane == 0) {
        if (k < KDIM)             out[1 + k] = s;
        else if (k < KDIM + NSTR) out[1 + KDIM + (k - KDIM)] = -s / volume[0];
        else                      out[0] = s;
    }
}

extern "C" void kernel_launch(void* const* d_in, const int* in_sizes, int n_in,
                              void* d_out, int out_size)
{
    const float* desc    = (const float*)d_in[0];
    const float* CG      = (const float*)d_in[1];
    const float* SG      = (const float*)d_in[2];
    const float* W0      = (const float*)d_in[3];
    const float* b0      = (const float*)d_in[4];
    const float* W1      = (const float*)d_in[5];
    const float* b1      = (const float*)d_in[6];
    const float* W2      = (const float*)d_in[7];
    const float* b2      = (const float*)d_in[8];
    const float* volume  = (const float*)d_in[9];
    const int*   species = (const int*)  d_in[10];
    float* out = (float*)d_out;

    const int mlp_smem = (2 * DDIM * WS + 4 * TILE * XS + MLP_THREADS) * sizeof(float); // ~144 KB
    cudaFuncSetAttribute(nnp_mlp_kernel,
                         cudaFuncAttributeMaxDynamicSharedMemorySize, mlp_smem);

    nnp_mlp_kernel<<<NTILES_MAX, MLP_THREADS, mlp_smem>>>(
        desc, SG, W0, b0, W1, b1, W2, b2, species);
    nnp_stream_kernel<<<NATOMS * 6, 256>>>(CG);
    nnp_reduce_kernel<<<(KTOT + 7) / 8, 256>>>(out, volume);
}

// round 10
// speedup vs baseline: 1.0733x; 1.0168x over previous
#include <cuda_runtime.h>
#include <cstddef>

#define NATOMS 512
#define DDIM   128
#define KDIM   1536   // 3*N
#define NSTR   6
#define KTOT   (KDIM + NSTR + 1)
#define NSPEC  4
#define TILE   4      // atoms per MLP block
#define XS     132    // activation smem row stride (floats)
#define WS     132    // weight smem row stride (floats), 16B-aligned rows
#define WS64   66     // in u64 units
#define NTILES_MAX (NATOMS / TILE + NSPEC - 1)   // 131
#define MLP_THREADS 512

typedef unsigned long long u64;

#define FMA_F32X2(d, a, b, c) \
    asm("fma.rn.f32x2 %0, %1, %2, %3;" : "=l"(d) : "l"(a), "l"(b), "l"(c))
#define PACK2_F32X2(out, v) \
    asm("mov.b64 %0, {%1, %1};" : "=l"(out) : "r"(__float_as_uint(v)))

__device__ __forceinline__ float f32x2_lo(u64 v) { return __uint_as_float((unsigned)(v & 0xFFFFFFFFu)); }
__device__ __forceinline__ float f32x2_hi(u64 v) { return __uint_as_float((unsigned)(v >> 32)); }
__device__ __forceinline__ float f32x2_sum(u64 v) { return f32x2_lo(v) + f32x2_hi(v); }

// Scratch
__device__ __align__(16) float g_partial[KDIM * NATOMS];        // force partials (3 MB)
__device__ __align__(16) float g_separt[(NSTR + 1) * NATOMS];   // stress + energy partials
__device__ __align__(16) float g_G[NATOMS * DDIM];              // per-atom dE/ddesc

// ---------------------------------------------------------------------------
// Kernel 1: species-batched MLP fwd+bwd. 131 blocks x 512 threads.
// Forward: thread = (row ty, atom tx), LDS.128 weight loads, 4 FMA chains.
// Backward: thread = (jj-half h, atom ax, row-pair r2); split-K with smem
// partial combine — all 512 threads active, LDS.64 weight loads.
// ---------------------------------------------------------------------------
__global__ __launch_bounds__(MLP_THREADS) void nnp_mlp_kernel(
    const float* __restrict__ desc,   // [N, D]
    const float* __restrict__ SG,     // [N, 6, D]
    const float* __restrict__ W0,     // [S, H, D]
    const float* __restrict__ b0,     // [S, H]
    const float* __restrict__ W1,     // [S, H, H]
    const float* __restrict__ b1,     // [S, H]
    const float* __restrict__ W2,     // [S, 1, H]
    const float* __restrict__ b2,     // [S, 1]
    const int*   __restrict__ species)
{
    const int tid  = threadIdx.x;
    const int ty   = tid >> 2;     // fwd: row 0..127
    const int tx   = tid & 3;      // fwd: atom
    const int wid  = tid >> 5;     // 0..15
    const int lane = tid & 31;
    // backward mapping
    const int h   = tid >> 8;           // jj half 0/1
    const int r2  = (tid >> 2) & 63;    // row pair -> rows r2*2, r2*2+1
    const int ax  = tid & 3;            // atom

    extern __shared__ float sm[];
    float* W0s = sm;                      // 128*132
    float* W1s = sm + DDIM * WS;          // 128*132
    float* X   = sm + 2 * DDIM * WS;      // TILE*XS
    float* H0  = X  + TILE * XS;          // h0, later G
    float* A0  = H0 + TILE * XS;          // 1-h0^2, later d0
    float* D1  = A0 + TILE * XS;
    float* Ep  = D1 + TILE * XS;          // 512 energy partials
    float* Pb  = Ep + MLP_THREADS;        // 512 backward partials
    __shared__ int sSpec[NATOMS];
    __shared__ int idx[TILE];
    __shared__ int sh_cnt[NSPEC];
    __shared__ int sh_s, sh_j, sh_m;

    sSpec[tid] = species[tid];
    __syncthreads();

    // ---- species counts (warp 0, smem ballots) ----
    if (wid == 0) {
        int c0 = 0, c1 = 0, c2 = 0, c3 = 0;
        #pragma unroll
        for (int c = 0; c < NATOMS; c += 32) {
            const int spv = sSpec[c + lane];
            c0 += __popc(__ballot_sync(0xFFFFFFFFu, spv == 0));
            c1 += __popc(__ballot_sync(0xFFFFFFFFu, spv == 1));
            c2 += __popc(__ballot_sync(0xFFFFFFFFu, spv == 2));
            c3 += __popc(__ballot_sync(0xFFFFFFFFu, spv == 3));
        }
        if (lane == 0) { sh_cnt[0] = c0; sh_cnt[1] = c1; sh_cnt[2] = c2; sh_cnt[3] = c3; }
    }
    __syncthreads();

    if (tid == 0) {
        int b = blockIdx.x, sp = 0, acc = 0;
        for (; sp < NSPEC; sp++) {
            const int t = (sh_cnt[sp] + TILE - 1) / TILE;
            if (b < acc + t) break;
            acc += t;
        }
        sh_s = sp;
        if (sp < NSPEC) {
            const int jj = b - acc;
            sh_j = jj;
            const int mm = sh_cnt[sp] - jj * TILE;
            sh_m = mm > TILE ? TILE : mm;
        }
    }
    __syncthreads();
    const int s = sh_s;
    if (s >= NSPEC) return;
    const int j = sh_j;
    const int m = sh_m;

    // per-row bias prefetch (fwd mapping)
    const float pb0 = b0[s * DDIM + ty];
    const float pb1 = b1[s * DDIM + ty];
    const float pw2 = W2[s * DDIM + ty];
    const float pb2 = b2[s];

    // ---- atom indices (warp 0) ----
    if (wid == 0) {
        int base = 0;
        #pragma unroll
        for (int c = 0; c < NATOMS; c += 32) {
            const int spv = sSpec[c + lane];
            const unsigned mask = __ballot_sync(0xFFFFFFFFu, spv == s);
            if (spv == s) {
                const int rank = base + __popc(mask & ((1u << lane) - 1u));
                const int rel = rank - j * TILE;
                if (rel >= 0 && rel < TILE) idx[rel] = c + lane;
            }
            base += __popc(mask);
        }
    }
    __syncthreads();

    // ---- prefetch SG stress rows ----
    float4 sv[2]; int srs[2], sn[2], sa[2]; bool svd[2];
    #pragma unroll
    for (int q = 0; q < 2; q++) {
        const int t = wid + q * 16;
        svd[q] = t < NSTR * m;
        srs[q] = 0; sn[q] = 0; sa[q] = 0;
        if (svd[q]) {
            sa[q] = t / NSTR; srs[q] = t % NSTR; sn[q] = idx[sa[q]];
            sv[q] = ((const float4*)(SG + ((size_t)sn[q] * NSTR + srs[q]) * DDIM))[lane];
        }
    }

    // ---- stage descriptors + W0/W1 (float4, aligned rows) ----
    {
        const int a = tid >> 7, d = tid & 127;
        X[a * XS + d] = (a < m) ? desc[(size_t)idx[a] * DDIM + d] : 0.f;
    }
    {
        const float4* w0g = (const float4*)(W0 + (size_t)s * DDIM * DDIM);
        const float4* w1g = (const float4*)(W1 + (size_t)s * DDIM * DDIM);
        #pragma unroll 8
        for (int f = tid; f < DDIM * 32; f += MLP_THREADS) {
            const int r = f >> 5, d4 = f & 31;
            *(float4*)(W0s + r * WS + d4 * 4) = w0g[f];
            *(float4*)(W1s + r * WS + d4 * 4) = w1g[f];
        }
    }
    __syncthreads();

    // ---- forward layer 0: LDS.128 weights, 4 chains ----
    {
        u64 a0 = 0ull, a1 = 0ull, a2 = 0ull, a3 = 0ull;
        const ulonglong2* Xd = (const ulonglong2*)(X + tx * XS);
        const ulonglong2* Wd = (const ulonglong2*)(W0s + (size_t)ty * WS);
        #pragma unroll
        for (int dq = 0; dq < 32; dq += 2) {
            ulonglong2 w0v = Wd[dq],     x0v = Xd[dq];
            ulonglong2 w1v = Wd[dq + 1], x1v = Xd[dq + 1];
            FMA_F32X2(a0, w0v.x, x0v.x, a0);
            FMA_F32X2(a1, w0v.y, x0v.y, a1);
            FMA_F32X2(a2, w1v.x, x1v.x, a2);
            FMA_F32X2(a3, w1v.y, x1v.y, a3);
        }
        const float hv = tanhf((f32x2_sum(a0) + f32x2_sum(a1))
                             + (f32x2_sum(a2) + f32x2_sum(a3)) + pb0);
        H0[tx * XS + ty] = hv;
        A0[tx * XS + ty] = 1.f - hv * hv;
    }
    __syncthreads();

    // ---- forward layer 1 + output partials ----
    {
        u64 a0 = 0ull, a1 = 0ull, a2 = 0ull, a3 = 0ull;
        const ulonglong2* Xd = (const ulonglong2*)(H0 + tx * XS);
        const ulonglong2* Wd = (const ulonglong2*)(W1s + (size_t)ty * WS);
        #pragma unroll
        for (int dq = 0; dq < 32; dq += 2) {
            ulonglong2 w0v = Wd[dq],     x0v = Xd[dq];
            ulonglong2 w1v = Wd[dq + 1], x1v = Xd[dq + 1];
            FMA_F32X2(a0, w0v.x, x0v.x, a0);
            FMA_F32X2(a1, w0v.y, x0v.y, a1);
            FMA_F32X2(a2, w1v.x, x1v.x, a2);
            FMA_F32X2(a3, w1v.y, x1v.y, a3);
        }
        const float hv = tanhf((f32x2_sum(a0) + f32x2_sum(a1))
                             + (f32x2_sum(a2) + f32x2_sum(a3)) + pb1);
        Ep[tid] = pw2 * hv;
        D1[tx * XS + ty] = pw2 * (1.f - hv * hv);
    }
    __syncthreads();

    // ---- energy per atom ----
    if (tid < m) {
        float e0 = pb2, e1 = 0.f, e2 = 0.f, e3 = 0.f;
        #pragma unroll 8
        for (int t2 = 0; t2 < 128; t2 += 4) {
            e0 += Ep[(t2 + 0) * 4 + tid];
            e1 += Ep[(t2 + 1) * 4 + tid];
            e2 += Ep[(t2 + 2) * 4 + tid];
            e3 += Ep[(t2 + 3) * 4 + tid];
        }
        g_separt[NSTR * NATOMS + idx[tid]] = (e0 + e1) + (e2 + e3);
    }

    // ---- backward B1: D0 = (W1^T @ D1) * A0, split-K over 2 halves ----
    u64 bacc0, bacc1;
    {
        u64 acc0 = 0ull, acc1 = 0ull;
        const int jbase = h * 64;
        const float4* Dp = (const float4*)(D1 + ax * XS + jbase);
        const u64* Wb = (const u64*)W1s;
        #pragma unroll
        for (int jq = 0; jq < 16; jq++) {
            const float4 dv = Dp[jq];
            u64 da, db, dc, dd;
            PACK2_F32X2(da, dv.x); PACK2_F32X2(db, dv.y);
            PACK2_F32X2(dc, dv.z); PACK2_F32X2(dd, dv.w);
            const size_t wb = (size_t)(jbase + jq * 4) * WS64 + r2;
            FMA_F32X2(acc0, Wb[wb + 0 * WS64], da, acc0);
            FMA_F32X2(acc1, Wb[wb + 1 * WS64], db, acc1);
            FMA_F32X2(acc0, Wb[wb + 2 * WS64], dc, acc0);
            FMA_F32X2(acc1, Wb[wb + 3 * WS64], dd, acc1);
        }
        bacc0 = acc0; bacc1 = acc1;
    }
    if (h == 1) {
        Pb[ax * DDIM + r2 * 2 + 0] = f32x2_lo(bacc0) + f32x2_lo(bacc1);
        Pb[ax * DDIM + r2 * 2 + 1] = f32x2_hi(bacc0) + f32x2_hi(bacc1);
    }
    __syncthreads();
    if (h == 0) {
        A0[ax * XS + r2 * 2 + 0] *= f32x2_lo(bacc0) + f32x2_lo(bacc1) + Pb[ax * DDIM + r2 * 2 + 0];
        A0[ax * XS + r2 * 2 + 1] *= f32x2_hi(bacc0) + f32x2_hi(bacc1) + Pb[ax * DDIM + r2 * 2 + 1];
    }
    __syncthreads();

    // ---- backward B2: G = W0^T @ D0, split-K ----
    {
        u64 acc0 = 0ull, acc1 = 0ull;
        const int jbase = h * 64;
        const float4* Dp = (const float4*)(A0 + ax * XS + jbase);
        const u64* Wb = (const u64*)W0s;
        #pragma unroll
        for (int jq = 0; jq < 16; jq++) {
            const float4 dv = Dp[jq];
            u64 da, db, dc, dd;
            PACK2_F32X2(da, dv.x); PACK2_F32X2(db, dv.y);
            PACK2_F32X2(dc, dv.z); PACK2_F32X2(dd, dv.w);
            const size_t wb = (size_t)(jbase + jq * 4) * WS64 + r2;
            FMA_F32X2(acc0, Wb[wb + 0 * WS64], da, acc0);
            FMA_F32X2(acc1, Wb[wb + 1 * WS64], db, acc1);
            FMA_F32X2(acc0, Wb[wb + 2 * WS64], dc, acc0);
            FMA_F32X2(acc1, Wb[wb + 3 * WS64], dd, acc1);
        }
        bacc0 = acc0; bacc1 = acc1;
    }
    if (h == 1) {
        Pb[ax * DDIM + r2 * 2 + 0] = f32x2_lo(bacc0) + f32x2_lo(bacc1);
        Pb[ax * DDIM + r2 * 2 + 1] = f32x2_hi(bacc0) + f32x2_hi(bacc1);
    }
    __syncthreads();
    if (h == 0) {
        const float g0 = f32x2_lo(bacc0) + f32x2_lo(bacc1) + Pb[ax * DDIM + r2 * 2 + 0];
        const float g1 = f32x2_hi(bacc0) + f32x2_hi(bacc1) + Pb[ax * DDIM + r2 * 2 + 1];
        H0[ax * XS + r2 * 2 + 0] = g0;
        H0[ax * XS + r2 * 2 + 1] = g1;
        if (ax < m)
            *(float2*)(g_G + (size_t)idx[ax] * DDIM + r2 * 2) = make_float2(g0, g1);
    }
    __syncthreads();

    // ---- stress partials (SG in registers, 16 warps) ----
    #pragma unroll
    for (int q = 0; q < 2; q++) {
        if (svd[q]) {
            const float4 g = ((const float4*)(H0 + sa[q] * XS))[lane];
            float svv = sv[q].x * g.x + sv[q].y * g.y + sv[q].z * g.z + sv[q].w * g.w;
            #pragma unroll
            for (int off = 16; off > 0; off >>= 1)
                svv += __shfl_xor_sync(0xFFFFFFFFu, svv, off);
            if (lane == 0) g_separt[(size_t)srs[q] * NATOMS + sn[q]] = svv;
        }
    }
}

// ---------------------------------------------------------------------------
// Kernel 2: stream coord_grads (403 MB), atom-major — measured ~roofline.
// ---------------------------------------------------------------------------
__global__ __launch_bounds__(256) void nnp_stream_kernel(
    const float* __restrict__ CG)     // [N, KDIM, D]
{
    const int b    = blockIdx.x;
    const int n    = b / 6;
    const int chnk = b % 6;
    const int wid  = threadIdx.x >> 5;
    const int lane = threadIdx.x & 31;

    const float4 gv = reinterpret_cast<const float4*>(g_G + (size_t)n * DDIM)[lane];

    const int k0 = chnk * 256 + wid * 32;
    const float4* base = reinterpret_cast<const float4*>(
        CG + ((size_t)n * KDIM + k0) * DDIM);
    float* outp = g_partial + (size_t)k0 * NATOMS + n;

    #pragma unroll
    for (int it = 0; it < 8; it++) {
        const float4* p = base + (size_t)(it * 4) * 32 + lane;
        float4 v0 = __ldcs(p + 0 * 32);
        float4 v1 = __ldcs(p + 1 * 32);
        float4 v2 = __ldcs(p + 2 * 32);
        float4 v3 = __ldcs(p + 3 * 32);
        float s0 = v0.x * gv.x + v0.y * gv.y + v0.z * gv.z + v0.w * gv.w;
        float s1 = v1.x * gv.x + v1.y * gv.y + v1.z * gv.z + v1.w * gv.w;
        float s2 = v2.x * gv.x + v2.y * gv.y + v2.z * gv.z + v2.w * gv.w;
        float s3 = v3.x * gv.x + v3.y * gv.y + v3.z * gv.z + v3.w * gv.w;
        #pragma unroll
        for (int off = 16; off > 0; off >>= 1) {
            s0 += __shfl_xor_sync(0xFFFFFFFFu, s0, off);
            s1 += __shfl_xor_sync(0xFFFFFFFFu, s1, off);
            s2 += __shfl_xor_sync(0xFFFFFFFFu, s2, off);
            s3 += __shfl_xor_sync(0xFFFFFFFFu, s3, off);
        }
        if (lane == 0) {
            outp[(size_t)(it * 4 + 0) * NATOMS] = s0;
            outp[(size_t)(it * 4 + 1) * NATOMS] = s1;
            outp[(size_t)(it * 4 + 2) * NATOMS] = s2;
            outp[(size_t)(it * 4 + 3) * NATOMS] = s3;
        }
    }
}

// ---------------------------------------------------------------------------
// Kernel 3: deterministic reduce. Warp per output slot over 512 atoms.
// ---------------------------------------------------------------------------
__global__ void nnp_reduce_kernel(float* __restrict__ out,
                                  const float* __restrict__ volume)
{
    const int k    = blockIdx.x * 8 + (threadIdx.x >> 5);
    const int lane = threadIdx.x & 31;
    if (k >= KTOT) return;

    const float* src = (k < KDIM) ? (g_partial + (size_t)k * NATOMS)
                                  : (g_separt + (size_t)(k - KDIM) * NATOMS);
    const float4* base = reinterpret_cast<const float4*>(src);
    float4 v0 = base[lane + 0 * 32];
    float4 v1 = base[lane + 1 * 32];
    float4 v2 = base[lane + 2 * 32];
    float4 v3 = base[lane + 3 * 32];
    float s = (v0.x + v0.y + v0.z + v0.w) + (v1.x + v1.y + v1.z + v1.w)
            + (v2.x + v2.y + v2.z + v2.w) + (v3.x + v3.y + v3.z + v3.w);
    #pragma unroll
    for (int off = 16; off > 0; off >>= 1)
        s += __shfl_xor_sync(0xFFFFFFFFu, s, off);

    if (lane == 0) {
        if (k < KDIM)             out[1 + k] = s;
        else if (k < KDIM + NSTR) out[1 + KDIM + (k - KDIM)] = -s / volume[0];
        else                      out[0] = s;
    }
}

extern "C" void kernel_launch(void* const* d_in, const int* in_sizes, int n_in,
                              void* d_out, int out_size)
{
    const float* desc    = (const float*)d_in[0];
    const float* CG      = (const float*)d_in[1];
    const float* SG      = (const float*)d_in[2];
    const float* W0      = (const float*)d_in[3];
    const float* b0      = (const float*)d_in[4];
    const float* W1      = (const float*)d_in[5];
    const float* b1      = (const float*)d_in[6];
    const float* W2      = (const float*)d_in[7];
    const float* b2      = (const float*)d_in[8];
    const float* volume  = (const float*)d_in[9];
    const int*   species = (const int*)  d_in[10];
    float* out = (float*)d_out;

    const int mlp_smem = (2 * DDIM * WS + 4 * TILE * XS + 2 * MLP_THREADS) * sizeof(float); // ~148 KB
    cudaFuncSetAttribute(nnp_mlp_kernel,
                         cudaFuncAttributeMaxDynamicSharedMemorySize, mlp_smem);

    nnp_mlp_kernel<<<NTILES_MAX, MLP_THREADS, mlp_smem>>>(
        desc, SG, W0, b0, W1, b1, W2, b2, species);
    nnp_stream_kernel<<<NATOMS * 6, 256>>>(CG);
    nnp_reduce_kernel<<<(KTOT + 7) / 8, 256>>>(out, volume);
}

// round 11
// speedup vs baseline: 1.1688x; 1.0890x over previous
#include <cuda_runtime.h>
#include <cstddef>

#define NATOMS 512
#define DDIM   128
#define KDIM   1536   // 3*N
#define NSTR   6
#define KTOT   (KDIM + NSTR + 1)
#define NSPEC  4
#define TILE   4      // atoms per MLP block
#define XS     132    // activation smem row stride (floats)
#define WS     132    // weight smem row stride (floats), 16B-aligned rows
#define WS64   66     // in u64 units
#define NTILES_MAX (NATOMS / TILE + NSPEC - 1)   // 131
#define MLP_THREADS 512

typedef unsigned long long u64;

#define FMA_F32X2(d, a, b, c) \
    asm("fma.rn.f32x2 %0, %1, %2, %3;" : "=l"(d) : "l"(a), "l"(b), "l"(c))
#define PACK2_F32X2(out, v) \
    asm("mov.b64 %0, {%1, %1};" : "=l"(out) : "r"(__float_as_uint(v)))

__device__ __forceinline__ float f32x2_lo(u64 v) { return __uint_as_float((unsigned)(v & 0xFFFFFFFFu)); }
__device__ __forceinline__ float f32x2_hi(u64 v) { return __uint_as_float((unsigned)(v >> 32)); }
__device__ __forceinline__ float f32x2_sum(u64 v) { return f32x2_lo(v) + f32x2_hi(v); }

// Scratch
__device__ __align__(16) float g_partial[KDIM * NATOMS];        // force partials (3 MB)
__device__ __align__(16) float g_separt[(NSTR + 1) * NATOMS];   // stress + energy partials
__device__ __align__(16) float g_G[NATOMS * DDIM];              // per-atom dE/ddesc
__device__ int   g_flag[NATOMS];                                // per-atom G-ready flags
__device__ float g_dummy;                                       // keep-alive sink (never read)

// ---------------------------------------------------------------------------
// Kernel 1: species-batched MLP fwd+bwd (R10 structure) + PDL + flag release.
// ---------------------------------------------------------------------------
__global__ __launch_bounds__(MLP_THREADS) void nnp_mlp_kernel(
    const float* __restrict__ desc,   // [N, D]
    const float* __restrict__ SG,     // [N, 6, D]
    const float* __restrict__ W0,     // [S, H, D]
    const float* __restrict__ b0,     // [S, H]
    const float* __restrict__ W1,     // [S, H, H]
    const float* __restrict__ b1,     // [S, H]
    const float* __restrict__ W2,     // [S, 1, H]
    const float* __restrict__ b2,     // [S, 1]
    const int*   __restrict__ species)
{
    asm volatile("griddepcontrol.launch_dependents;");

    const int tid  = threadIdx.x;
    const int ty   = tid >> 2;     // fwd: row 0..127
    const int tx   = tid & 3;      // fwd: atom
    const int wid  = tid >> 5;
    const int lane = tid & 31;
    const int h   = tid >> 8;           // bwd: jj half
    const int r2  = (tid >> 2) & 63;    // bwd: row pair
    const int ax  = tid & 3;            // bwd: atom

    extern __shared__ float sm[];
    float* W0s = sm;
    float* W1s = sm + DDIM * WS;
    float* X   = sm + 2 * DDIM * WS;
    float* H0  = X  + TILE * XS;
    float* A0  = H0 + TILE * XS;
    float* D1  = A0 + TILE * XS;
    float* Ep  = D1 + TILE * XS;
    float* Pb  = Ep + MLP_THREADS;
    __shared__ int sSpec[NATOMS];
    __shared__ int idx[TILE];
    __shared__ int sh_cnt[NSPEC];
    __shared__ int sh_s, sh_j, sh_m;

    sSpec[tid] = species[tid];
    __syncthreads();

    if (wid == 0) {
        int c0 = 0, c1 = 0, c2 = 0, c3 = 0;
        #pragma unroll
        for (int c = 0; c < NATOMS; c += 32) {
            const int spv = sSpec[c + lane];
            c0 += __popc(__ballot_sync(0xFFFFFFFFu, spv == 0));
            c1 += __popc(__ballot_sync(0xFFFFFFFFu, spv == 1));
            c2 += __popc(__ballot_sync(0xFFFFFFFFu, spv == 2));
            c3 += __popc(__ballot_sync(0xFFFFFFFFu, spv == 3));
        }
        if (lane == 0) { sh_cnt[0] = c0; sh_cnt[1] = c1; sh_cnt[2] = c2; sh_cnt[3] = c3; }
    }
    __syncthreads();

    if (tid == 0) {
        int b = blockIdx.x, sp = 0, acc = 0;
        for (; sp < NSPEC; sp++) {
            const int t = (sh_cnt[sp] + TILE - 1) / TILE;
            if (b < acc + t) break;
            acc += t;
        }
        sh_s = sp;
        if (sp < NSPEC) {
            const int jj = b - acc;
            sh_j = jj;
            const int mm = sh_cnt[sp] - jj * TILE;
            sh_m = mm > TILE ? TILE : mm;
        }
    }
    __syncthreads();
    const int s = sh_s;
    if (s >= NSPEC) return;
    const int j = sh_j;
    const int m = sh_m;

    const float pb0 = b0[s * DDIM + ty];
    const float pb1 = b1[s * DDIM + ty];
    const float pw2 = W2[s * DDIM + ty];
    const float pb2 = b2[s];

    if (wid == 0) {
        int base = 0;
        #pragma unroll
        for (int c = 0; c < NATOMS; c += 32) {
            const int spv = sSpec[c + lane];
            const unsigned mask = __ballot_sync(0xFFFFFFFFu, spv == s);
            if (spv == s) {
                const int rank = base + __popc(mask & ((1u << lane) - 1u));
                const int rel = rank - j * TILE;
                if (rel >= 0 && rel < TILE) idx[rel] = c + lane;
            }
            base += __popc(mask);
        }
    }
    __syncthreads();

    float4 sv[2]; int srs[2], sn[2], sa[2]; bool svd[2];
    #pragma unroll
    for (int q = 0; q < 2; q++) {
        const int t = wid + q * 16;
        svd[q] = t < NSTR * m;
        srs[q] = 0; sn[q] = 0; sa[q] = 0;
        if (svd[q]) {
            sa[q] = t / NSTR; srs[q] = t % NSTR; sn[q] = idx[sa[q]];
            sv[q] = ((const float4*)(SG + ((size_t)sn[q] * NSTR + srs[q]) * DDIM))[lane];
        }
    }

    {
        const int a = tid >> 7, d = tid & 127;
        X[a * XS + d] = (a < m) ? desc[(size_t)idx[a] * DDIM + d] : 0.f;
    }
    {
        const float4* w0g = (const float4*)(W0 + (size_t)s * DDIM * DDIM);
        const float4* w1g = (const float4*)(W1 + (size_t)s * DDIM * DDIM);
        #pragma unroll 8
        for (int f = tid; f < DDIM * 32; f += MLP_THREADS) {
            const int r = f >> 5, d4 = f & 31;
            *(float4*)(W0s + r * WS + d4 * 4) = w0g[f];
            *(float4*)(W1s + r * WS + d4 * 4) = w1g[f];
        }
    }
    __syncthreads();

    // ---- forward layer 0 ----
    {
        u64 a0 = 0ull, a1 = 0ull, a2 = 0ull, a3 = 0ull;
        const ulonglong2* Xd = (const ulonglong2*)(X + tx * XS);
        const ulonglong2* Wd = (const ulonglong2*)(W0s + (size_t)ty * WS);
        #pragma unroll
        for (int dq = 0; dq < 32; dq += 2) {
            ulonglong2 w0v = Wd[dq],     x0v = Xd[dq];
            ulonglong2 w1v = Wd[dq + 1], x1v = Xd[dq + 1];
            FMA_F32X2(a0, w0v.x, x0v.x, a0);
            FMA_F32X2(a1, w0v.y, x0v.y, a1);
            FMA_F32X2(a2, w1v.x, x1v.x, a2);
            FMA_F32X2(a3, w1v.y, x1v.y, a3);
        }
        const float hv = tanhf((f32x2_sum(a0) + f32x2_sum(a1))
                             + (f32x2_sum(a2) + f32x2_sum(a3)) + pb0);
        H0[tx * XS + ty] = hv;
        A0[tx * XS + ty] = 1.f - hv * hv;
    }
    __syncthreads();

    // ---- forward layer 1 + output partials ----
    {
        u64 a0 = 0ull, a1 = 0ull, a2 = 0ull, a3 = 0ull;
        const ulonglong2* Xd = (const ulonglong2*)(H0 + tx * XS);
        const ulonglong2* Wd = (const ulonglong2*)(W1s + (size_t)ty * WS);
        #pragma unroll
        for (int dq = 0; dq < 32; dq += 2) {
            ulonglong2 w0v = Wd[dq],     x0v = Xd[dq];
            ulonglong2 w1v = Wd[dq + 1], x1v = Xd[dq + 1];
            FMA_F32X2(a0, w0v.x, x0v.x, a0);
            FMA_F32X2(a1, w0v.y, x0v.y, a1);
            FMA_F32X2(a2, w1v.x, x1v.x, a2);
            FMA_F32X2(a3, w1v.y, x1v.y, a3);
        }
        const float hv = tanhf((f32x2_sum(a0) + f32x2_sum(a1))
                             + (f32x2_sum(a2) + f32x2_sum(a3)) + pb1);
        Ep[tid] = pw2 * hv;
        D1[tx * XS + ty] = pw2 * (1.f - hv * hv);
    }
    __syncthreads();

    if (tid < m) {
        float e0 = pb2, e1 = 0.f, e2 = 0.f, e3 = 0.f;
        #pragma unroll 8
        for (int t2 = 0; t2 < 128; t2 += 4) {
            e0 += Ep[(t2 + 0) * 4 + tid];
            e1 += Ep[(t2 + 1) * 4 + tid];
            e2 += Ep[(t2 + 2) * 4 + tid];
            e3 += Ep[(t2 + 3) * 4 + tid];
        }
        g_separt[NSTR * NATOMS + idx[tid]] = (e0 + e1) + (e2 + e3);
    }

    // ---- backward B1: D0 = (W1^T @ D1) * A0, split-K ----
    u64 bacc0, bacc1;
    {
        u64 acc0 = 0ull, acc1 = 0ull;
        const int jbase = h * 64;
        const float4* Dp = (const float4*)(D1 + ax * XS + jbase);
        const u64* Wb = (const u64*)W1s;
        #pragma unroll
        for (int jq = 0; jq < 16; jq++) {
            const float4 dv = Dp[jq];
            u64 da, db, dc, dd;
            PACK2_F32X2(da, dv.x); PACK2_F32X2(db, dv.y);
            PACK2_F32X2(dc, dv.z); PACK2_F32X2(dd, dv.w);
            const size_t wb = (size_t)(jbase + jq * 4) * WS64 + r2;
            FMA_F32X2(acc0, Wb[wb + 0 * WS64], da, acc0);
            FMA_F32X2(acc1, Wb[wb + 1 * WS64], db, acc1);
            FMA_F32X2(acc0, Wb[wb + 2 * WS64], dc, acc0);
            FMA_F32X2(acc1, Wb[wb + 3 * WS64], dd, acc1);
        }
        bacc0 = acc0; bacc1 = acc1;
    }
    if (h == 1) {
        Pb[ax * DDIM + r2 * 2 + 0] = f32x2_lo(bacc0) + f32x2_lo(bacc1);
        Pb[ax * DDIM + r2 * 2 + 1] = f32x2_hi(bacc0) + f32x2_hi(bacc1);
    }
    __syncthreads();
    if (h == 0) {
        A0[ax * XS + r2 * 2 + 0] *= f32x2_lo(bacc0) + f32x2_lo(bacc1) + Pb[ax * DDIM + r2 * 2 + 0];
        A0[ax * XS + r2 * 2 + 1] *= f32x2_hi(bacc0) + f32x2_hi(bacc1) + Pb[ax * DDIM + r2 * 2 + 1];
    }
    __syncthreads();

    // ---- backward B2: G = W0^T @ D0, split-K ----
    {
        u64 acc0 = 0ull, acc1 = 0ull;
        const int jbase = h * 64;
        const float4* Dp = (const float4*)(A0 + ax * XS + jbase);
        const u64* Wb = (const u64*)W0s;
        #pragma unroll
        for (int jq = 0; jq < 16; jq++) {
            const float4 dv = Dp[jq];
            u64 da, db, dc, dd;
            PACK2_F32X2(da, dv.x); PACK2_F32X2(db, dv.y);
            PACK2_F32X2(dc, dv.z); PACK2_F32X2(dd, dv.w);
            const size_t wb = (size_t)(jbase + jq * 4) * WS64 + r2;
            FMA_F32X2(acc0, Wb[wb + 0 * WS64], da, acc0);
            FMA_F32X2(acc1, Wb[wb + 1 * WS64], db, acc1);
            FMA_F32X2(acc0, Wb[wb + 2 * WS64], dc, acc0);
            FMA_F32X2(acc1, Wb[wb + 3 * WS64], dd, acc1);
        }
        bacc0 = acc0; bacc1 = acc1;
    }
    if (h == 1) {
        Pb[ax * DDIM + r2 * 2 + 0] = f32x2_lo(bacc0) + f32x2_lo(bacc1);
        Pb[ax * DDIM + r2 * 2 + 1] = f32x2_hi(bacc0) + f32x2_hi(bacc1);
    }
    __syncthreads();
    if (h == 0) {
        const float g0 = f32x2_lo(bacc0) + f32x2_lo(bacc1) + Pb[ax * DDIM + r2 * 2 + 0];
        const float g1 = f32x2_hi(bacc0) + f32x2_hi(bacc1) + Pb[ax * DDIM + r2 * 2 + 1];
        H0[ax * XS + r2 * 2 + 0] = g0;
        H0[ax * XS + r2 * 2 + 1] = g1;
        if (ax < m)
            *(float2*)(g_G + (size_t)idx[ax] * DDIM + r2 * 2) = make_float2(g0, g1);
    }
    __syncthreads();

    // ---- release per-atom flags (G complete + visible) ----
    if (tid < m) {
        __threadfence();
        ((volatile int*)g_flag)[idx[tid]] = 1;
    }

    // ---- stress partials ----
    #pragma unroll
    for (int q = 0; q < 2; q++) {
        if (svd[q]) {
            const float4 g = ((const float4*)(H0 + sa[q] * XS))[lane];
            float svv = sv[q].x * g.x + sv[q].y * g.y + sv[q].z * g.z + sv[q].w * g.w;
            #pragma unroll
            for (int off = 16; off > 0; off >>= 1)
                svv += __shfl_xor_sync(0xFFFFFFFFu, svv, off);
            if (lane == 0) g_separt[(size_t)srs[q] * NATOMS + sn[q]] = svv;
        }
    }
}

// ---------------------------------------------------------------------------
// Kernel 2: stream coord_grads. PDL-launched: if G not ready, prefetch own
// 128KB slab into L2 (useful DRAM work), then spin; else proceed directly.
// ---------------------------------------------------------------------------
__global__ __launch_bounds__(256) void nnp_stream_kernel(
    const float* __restrict__ CG)     // [N, KDIM, D]
{
    const int b    = blockIdx.x;
    const int n    = b / 6;
    const int chnk = b % 6;
    const int wid  = threadIdx.x >> 5;
    const int lane = threadIdx.x & 31;

    const int k0 = chnk * 256 + wid * 32;
    const float4* base = reinterpret_cast<const float4*>(
        CG + ((size_t)n * KDIM + k0) * DDIM);

    __shared__ int s_ready;
    if (threadIdx.x == 0) s_ready = ((volatile int*)g_flag)[n];
    __syncthreads();

    if (!s_ready) {
        // Prefetch this block's whole 128KB slab into L2 (discard-sum keeps
        // the loads alive; the sink condition is never true in practice).
        const float4* pf = reinterpret_cast<const float4*>(
            CG + ((size_t)n * KDIM + chnk * 256) * DDIM) + threadIdx.x;
        float ax = 0.f, ay = 0.f, az = 0.f, aw = 0.f;
        #pragma unroll 8
        for (int i = 0; i < 32; i++) {
            float4 v = __ldcg(pf + i * 256);
            ax += v.x; ay += v.y; az += v.z; aw += v.w;
        }
        if (__float_as_uint((ax + ay) + (az + aw)) == 0xDEADBEEFu)
            g_dummy = ax;
        if (threadIdx.x == 0) {
            while (((volatile int*)g_flag)[n] == 0) __nanosleep(128);
            __threadfence();
        }
    }
    __syncthreads();

    const float4 gv = reinterpret_cast<const float4*>(g_G + (size_t)n * DDIM)[lane];
    float* outp = g_partial + (size_t)k0 * NATOMS + n;

    #pragma unroll
    for (int it = 0; it < 8; it++) {
        const float4* p = base + (size_t)(it * 4) * 32 + lane;
        float4 v0 = __ldcs(p + 0 * 32);
        float4 v1 = __ldcs(p + 1 * 32);
        float4 v2 = __ldcs(p + 2 * 32);
        float4 v3 = __ldcs(p + 3 * 32);
        float s0 = v0.x * gv.x + v0.y * gv.y + v0.z * gv.z + v0.w * gv.w;
        float s1 = v1.x * gv.x + v1.y * gv.y + v1.z * gv.z + v1.w * gv.w;
        float s2 = v2.x * gv.x + v2.y * gv.y + v2.z * gv.z + v2.w * gv.w;
        float s3 = v3.x * gv.x + v3.y * gv.y + v3.z * gv.z + v3.w * gv.w;
        #pragma unroll
        for (int off = 16; off > 0; off >>= 1) {
            s0 += __shfl_xor_sync(0xFFFFFFFFu, s0, off);
            s1 += __shfl_xor_sync(0xFFFFFFFFu, s1, off);
            s2 += __shfl_xor_sync(0xFFFFFFFFu, s2, off);
            s3 += __shfl_xor_sync(0xFFFFFFFFu, s3, off);
        }
        if (lane == 0) {
            outp[(size_t)(it * 4 + 0) * NATOMS] = s0;
            outp[(size_t)(it * 4 + 1) * NATOMS] = s1;
            outp[(size_t)(it * 4 + 2) * NATOMS] = s2;
            outp[(size_t)(it * 4 + 3) * NATOMS] = s3;
        }
    }
}

// ---------------------------------------------------------------------------
// Kernel 3: deterministic reduce + flag reset for graph replay.
// ---------------------------------------------------------------------------
__global__ void nnp_reduce_kernel(float* __restrict__ out,
                                  const float* __restrict__ volume)
{
    if (blockIdx.x == 0) {
        g_flag[threadIdx.x]       = 0;
        g_flag[threadIdx.x + 256] = 0;
    }

    const int k    = blockIdx.x * 8 + (threadIdx.x >> 5);
    const int lane = threadIdx.x & 31;
    if (k >= KTOT) return;

    const float* src = (k < KDIM) ? (g_partial + (size_t)k * NATOMS)
                                  : (g_separt + (size_t)(k - KDIM) * NATOMS);
    const float4* base = reinterpret_cast<const float4*>(src);
    float4 v0 = base[lane + 0 * 32];
    float4 v1 = base[lane + 1 * 32];
    float4 v2 = base[lane + 2 * 32];
    float4 v3 = base[lane + 3 * 32];
    float s = (v0.x + v0.y + v0.z + v0.w) + (v1.x + v1.y + v1.z + v1.w)
            + (v2.x + v2.y + v2.z + v2.w) + (v3.x + v3.y + v3.z + v3.w);
    #pragma unroll
    for (int off = 16; off > 0; off >>= 1)
        s += __shfl_xor_sync(0xFFFFFFFFu, s, off);

    if (lane == 0) {
        if (k < KDIM)             out[1 + k] = s;
        else if (k < KDIM + NSTR) out[1 + KDIM + (k - KDIM)] = -s / volume[0];
        else                      out[0] = s;
    }
}

extern "C" void kernel_launch(void* const* d_in, const int* in_sizes, int n_in,
                              void* d_out, int out_size)
{
    const float* desc    = (const float*)d_in[0];
    const float* CG      = (const float*)d_in[1];
    const float* SG      = (const float*)d_in[2];
    const float* W0      = (const float*)d_in[3];
    const float* b0      = (const float*)d_in[4];
    const float* W1      = (const float*)d_in[5];
    const float* b1      = (const float*)d_in[6];
    const float* W2      = (const float*)d_in[7];
    const float* b2      = (const float*)d_in[8];
    const float* volume  = (const float*)d_in[9];
    const int*   species = (const int*)  d_in[10];
    float* out = (float*)d_out;

    const int mlp_smem = (2 * DDIM * WS + 4 * TILE * XS + 2 * MLP_THREADS) * sizeof(float);
    cudaFuncSetAttribute(nnp_mlp_kernel,
                         cudaFuncAttributeMaxDynamicSharedMemorySize, mlp_smem);

    nnp_mlp_kernel<<<NTILES_MAX, MLP_THREADS, mlp_smem>>>(
        desc, SG, W0, b0, W1, b1, W2, b2, species);

    // Stream kernel with programmatic dependent launch (overlaps with MLP).
    cudaLaunchConfig_t cfg = {};
    cfg.gridDim  = dim3(NATOMS * 6);
    cfg.blockDim = dim3(256);
    cfg.dynamicSmemBytes = 0;
    cfg.stream = 0;
    cudaLaunchAttribute attrs[1];
    attrs[0].id = cudaLaunchAttributeProgrammaticStreamSerialization;
    attrs[0].val.programmaticStreamSerializationAllowed = 1;
    cfg.attrs = attrs;
    cfg.numAttrs = 1;
    cudaLaunchKernelEx(&cfg, nnp_stream_kernel, CG);

    nnp_reduce_kernel<<<(KTOT + 7) / 8, 256>>>(out, volume);
}